// round 14
// baseline (speedup 1.0000x reference)
#include <cuda_runtime.h>
#include <cuda_fp16.h>
#include <cstdint>

// Problem dims
#define GB     4
#define GN_SEQ 4096
#define GH     16
#define GD     64
#define GC     1024
#define GM     16384          // GB*GN_SEQ
#define GK     1024
#define GNO    3072           // 3*GC

// GEMM tiling: CTA 128x128, 8 warps of 64x32, BKK=64, 3 stages, occ 2
#define BM 128
#define BN 128
#define BKK 64
#define STAGES 3
#define STAGE_BYTES 32768               // A 16K | B 16K
#define GEMM_SMEM (STAGES * STAGE_BYTES)  // 96 KB -> 2 CTAs/SM

// ---------------- scratch (static device globals; no allocation) -------------
__device__ __half g_Ah[(size_t)GM * GK];       // 32 MB x fp16
__device__ __half g_Wh[(size_t)GNO * GK];      //  6 MB w fp16
__device__ __half g_qkv16[(size_t)GM * GNO];   // 96 MB qkv logits fp16
__device__ float  g_cpart[64 * 4 * 64 * 64];
__device__ float  g_spart[64 * 4 * 64];
__device__ __half g_ctx16[64 * 64 * 64];       // normalized context fp16 [bh][d][e]
__device__ int    g_cnt[64];                   // per-bh completion counters (0-init)

// ---------------- asm helpers ------------------------------------------------
#define LDSM4(r, addr)                                                         \
    asm volatile("ldmatrix.sync.aligned.m8n8.x4.shared.b16 {%0,%1,%2,%3},[%4];"\
                 : "=r"((r)[0]), "=r"((r)[1]), "=r"((r)[2]), "=r"((r)[3])      \
                 : "r"(addr))

#define LDSM4T(r, addr)                                                        \
    asm volatile("ldmatrix.sync.aligned.m8n8.x4.trans.shared.b16 "             \
                 "{%0,%1,%2,%3},[%4];"                                         \
                 : "=r"((r)[0]), "=r"((r)[1]), "=r"((r)[2]), "=r"((r)[3])      \
                 : "r"(addr))

#define MMA_F16(d, a, b0, b1)                                                  \
    asm volatile("mma.sync.aligned.m16n8k16.row.col.f32.f16.f16.f32 "          \
                 "{%0,%1,%2,%3},{%4,%5,%6,%7},{%8,%9},{%0,%1,%2,%3};"          \
                 : "+f"((d)[0]), "+f"((d)[1]), "+f"((d)[2]), "+f"((d)[3])      \
                 : "r"((a)[0]), "r"((a)[1]), "r"((a)[2]), "r"((a)[3]),         \
                   "r"(b0), "r"(b1))

#define CP_ASYNC16(dst, src)                                                   \
    asm volatile("cp.async.cg.shared.global [%0],[%1],16;" ::                  \
                 "r"(dst), "l"(src) : "memory")
#define CP_COMMIT() asm volatile("cp.async.commit_group;" ::: "memory")
#define CP_WAIT1()  asm volatile("cp.async.wait_group 1;" ::: "memory")
#define CP_WAIT0()  asm volatile("cp.async.wait_group 0;" ::: "memory")

// ---------------- Kernel 0: fp32 -> fp16 convert pre-pass --------------------
__global__ __launch_bounds__(256) void split_kernel(const float* __restrict__ x,
                                                    const float* __restrict__ w)
{
    const size_t A4 = (size_t)GM * GK / 4;
    const size_t W4 = (size_t)GNO * GK / 4;
    const size_t total = A4 + W4;
    size_t stride = (size_t)gridDim.x * blockDim.x;
    for (size_t i = (size_t)blockIdx.x * blockDim.x + threadIdx.x; i < total; i += stride) {
        if (i < A4) {
            float4 v = ((const float4*)x)[i];
            __half2 h0 = __floats2half2_rn(v.x, v.y);
            __half2 h1 = __floats2half2_rn(v.z, v.w);
            *(uint2*)(g_Ah + i * 4) =
                make_uint2(*(unsigned*)&h0, *(unsigned*)&h1);
        } else {
            size_t j = i - A4;
            float4 v = ((const float4*)w)[j];
            __half2 h0 = __floats2half2_rn(v.x, v.y);
            __half2 h1 = __floats2half2_rn(v.z, v.w);
            *(uint2*)(g_Wh + j * 4) =
                make_uint2(*(unsigned*)&h0, *(unsigned*)&h1);
        }
    }
}

// ---------------- GEMM stage loader -------------------------------------------
__device__ __forceinline__ void issue_stage(int kt, int bm, int bn,
                                            unsigned sbase, int t)
{
    const int k0 = kt * BKK;
    const unsigned buf = sbase + (kt % STAGES) * STAGE_BYTES;
#pragma unroll
    for (int j = 0; j < 4; ++j) {
        int idx = t + j * 256;          // 0..1023
        int row = idx >> 3;
        int c   = idx & 7;
        unsigned soff = (unsigned)(row * 128 + ((c ^ (row & 7)) << 4));
        const __half* ga = g_Ah + (size_t)(bm + row) * GK + k0 + c * 8;
        CP_ASYNC16(buf + soff, ga);
        const __half* gb = g_Wh + (size_t)(bn + row) * GK + k0 + c * 8;
        CP_ASYNC16(buf + 16384 + soff, gb);
    }
}

// ---------------- Kernel 1: QKV GEMM (single fp16 MMA, fp32 acc, occ 2) -----
__global__ __launch_bounds__(256, 2) void qkv_gemm_f16()
{
    extern __shared__ char smraw[];
    const unsigned sbase = (unsigned)__cvta_generic_to_shared(smraw);

    const int t    = threadIdx.x;
    const int bn   = blockIdx.x * BN;
    const int bm   = blockIdx.y * BM;
    const int lane = t & 31;
    const int warp = t >> 5;
    const int wm   = warp >> 2;
    const int wn   = warp & 3;

    const int lr = lane & 15;
    const int ls = lane >> 4;
    unsigned off[4];
#pragma unroll
    for (int g = 0; g < 4; ++g)
        off[g] = (unsigned)(lr * 128 + (((2 * g) + ls) ^ (lr & 7)) * 16);

    float acc[4][4][4];
#pragma unroll
    for (int i = 0; i < 4; ++i)
#pragma unroll
        for (int j = 0; j < 4; ++j)
#pragma unroll
            for (int c = 0; c < 4; ++c) acc[i][j][c] = 0.0f;

    issue_stage(0, bm, bn, sbase, t); CP_COMMIT();
    issue_stage(1, bm, bn, sbase, t); CP_COMMIT();

    const int NT = GK / BKK;   // 16
    for (int kt = 0; kt < NT; ++kt) {
        CP_WAIT1();
        __syncthreads();
        if (kt + 2 < NT)
            issue_stage(kt + 2, bm, bn, sbase, t);
        CP_COMMIT();

        const unsigned slot = sbase + (kt % STAGES) * STAGE_BYTES;
        const unsigned aBs  = slot +         (wm * 64) * 128;
        const unsigned bBs  = slot + 16384 + (wn * 32) * 128;

#pragma unroll
        for (int ks = 0; ks < 4; ++ks) {
            unsigned ah[4][4], bb[2][4];
#pragma unroll
            for (int mt = 0; mt < 4; ++mt)
                LDSM4(ah[mt], aBs + mt * 2048 + off[ks]);
#pragma unroll
            for (int p = 0; p < 2; ++p)
                LDSM4(bb[p], bBs + p * 2048 + off[ks]);
#pragma unroll
            for (int mt = 0; mt < 4; ++mt)
#pragma unroll
                for (int p = 0; p < 2; ++p)
#pragma unroll
                    for (int j = 0; j < 2; ++j)
                        MMA_F16(acc[mt][p * 2 + j], ah[mt], bb[p][j], bb[p][j + 2]);
        }
    }

    // epilogue -> fp16 logits
    const int g  = lane >> 2;
    const int tc = lane & 3;
#pragma unroll
    for (int mt = 0; mt < 4; ++mt)
#pragma unroll
        for (int nt = 0; nt < 4; ++nt) {
            int row = bm + wm * 64 + mt * 16 + g;
            int col = bn + wn * 32 + nt * 8 + tc * 2;
            *(__half2*)(g_qkv16 + (size_t)row * GNO + col) =
                __floats2half2_rn(acc[mt][nt][0], acc[mt][nt][1]);
            *(__half2*)(g_qkv16 + (size_t)(row + 8) * GNO + col) =
                __floats2half2_rn(acc[mt][nt][2], acc[mt][nt][3]);
        }
}

// ---------------- Kernel 2: ctx partial via mma (pipelined) + fused reduce ---
__global__ __launch_bounds__(256) void ctx_partial_mma()
{
    const int bh    = blockIdx.x;
    const int chunk = blockIdx.y;
    const int b = bh >> 4, h = bh & 15;

    __shared__ __align__(16) __half sek[64 * 64];      // [n][d] swizzled
    __shared__ __align__(16) __half sv[2][64 * 64];    // double-buffered v
    __shared__ float ps[32][64];
    __shared__ int   s_last;

    const unsigned ekS = (unsigned)__cvta_generic_to_shared(sek);
    const unsigned vS  = (unsigned)__cvta_generic_to_shared(sv);

    const int t    = threadIdx.x;
    const int lane = t & 31;
    const int warp = t >> 5;
    const int wd   = warp >> 2;
    const int we   = warp & 3;

    const int rowA_l = (lane & 7) + ((lane >> 4) << 3);
    const int chA_l  = (lane >> 3) & 1;
    const int rowB_l = (lane & 7) + (((lane >> 3) & 1) << 3);
    const int chB_l  = lane >> 4;

    float acc[2][2][4];
#pragma unroll
    for (int i = 0; i < 2; ++i)
#pragma unroll
        for (int j = 0; j < 2; ++j)
#pragma unroll
            for (int c = 0; c < 4; ++c) acc[i][j][c] = 0.0f;
    float sacc[8] = {0, 0, 0, 0, 0, 0, 0, 0};

    const __half* kbase = g_qkv16 + ((size_t)b * GN_SEQ) * GNO + 1024 + h * 64;
    const __half* vbase = kbase + 1024;

    const int myrow = t >> 3;
    const int myc   = t & 7;
    const unsigned soff0 = (unsigned)(myrow * 128 + ((myc ^ (myrow & 7)) << 4));
    const unsigned soff1 = (unsigned)((myrow + 32) * 128 +
                                      ((myc ^ ((myrow + 32) & 7)) << 4));

    // prologue: prefetch k raw for tile 0, issue v load for tile 0
    uint4 kr0, kr1;
    {
        const int n0 = chunk * 1024;
        kr0 = *(const uint4*)(kbase + (size_t)(n0 + myrow) * GNO + myc * 8);
        kr1 = *(const uint4*)(kbase + (size_t)(n0 + myrow + 32) * GNO + myc * 8);
        CP_ASYNC16(vS + soff0, vbase + (size_t)(n0 + myrow) * GNO + myc * 8);
        CP_ASYNC16(vS + soff1, vbase + (size_t)(n0 + myrow + 32) * GNO + myc * 8);
        CP_COMMIT();
    }

    for (int tile = 0; tile < 16; ++tile) {
        const unsigned vbuf = vS + (unsigned)(tile & 1) * 8192;
        if (tile + 1 < 16) {
            const int n1 = chunk * 1024 + (tile + 1) * 64;
            const unsigned vnext = vS + (unsigned)((tile + 1) & 1) * 8192;
            CP_ASYNC16(vnext + soff0, vbase + (size_t)(n1 + myrow) * GNO + myc * 8);
            CP_ASYNC16(vnext + soff1, vbase + (size_t)(n1 + myrow + 32) * GNO + myc * 8);
        }
        CP_COMMIT();

        {
            const uint4 raws[2] = {kr0, kr1};
#pragma unroll
            for (int j = 0; j < 2; ++j) {
                const __half2* hp = (const __half2*)&raws[j];
                float e[8];
#pragma unroll
                for (int q = 0; q < 4; ++q) {
                    float2 f = __half22float2(hp[q]);
                    e[q * 2]     = __expf(f.x);
                    e[q * 2 + 1] = __expf(f.y);
                }
#pragma unroll
                for (int q = 0; q < 8; ++q) sacc[q] += e[q];
                uint4 outv;
                __half2* op = (__half2*)&outv;
#pragma unroll
                for (int q = 0; q < 4; ++q)
                    op[q] = __floats2half2_rn(e[q * 2], e[q * 2 + 1]);
                *(uint4*)((char*)sek + (j ? soff1 : soff0)) = outv;
            }
        }
        if (tile + 1 < 16) {
            const int n1 = chunk * 1024 + (tile + 1) * 64;
            kr0 = *(const uint4*)(kbase + (size_t)(n1 + myrow) * GNO + myc * 8);
            kr1 = *(const uint4*)(kbase + (size_t)(n1 + myrow + 32) * GNO + myc * 8);
        }
        CP_WAIT1();
        __syncthreads();

#pragma unroll
        for (int ks = 0; ks < 4; ++ks) {
            const int rA = ks * 16 + rowA_l;
            const int rB = ks * 16 + rowB_l;
            unsigned af[2][4], bf[4];
#pragma unroll
            for (int mt = 0; mt < 2; ++mt) {
                int ch = (wd * 4 + mt * 2 + chA_l) ^ (rA & 7);
                LDSM4T(af[mt], ekS + (unsigned)(rA * 128 + ch * 16));
            }
            {
                int ch = (we * 2 + chB_l) ^ (rB & 7);
                LDSM4T(bf, vbuf + (unsigned)(rB * 128 + ch * 16));
            }
#pragma unroll
            for (int mt = 0; mt < 2; ++mt)
#pragma unroll
                for (int j = 0; j < 2; ++j)
                    MMA_F16(acc[mt][j], af[mt], bf[2 * j], bf[2 * j + 1]);
        }
        __syncthreads();
    }

    // write C partials
    const int g   = lane >> 2;
    const int tc2 = (lane & 3) * 2;
    const size_t cbase = ((size_t)(bh * 4 + chunk)) * 4096;
#pragma unroll
    for (int mt = 0; mt < 2; ++mt)
#pragma unroll
        for (int j = 0; j < 2; ++j) {
            int d = wd * 32 + mt * 16 + g;
            int e = we * 16 + j * 8 + tc2;
            *(float2*)(g_cpart + cbase + d * 64 + e) =
                make_float2(acc[mt][j][0], acc[mt][j][1]);
            *(float2*)(g_cpart + cbase + (d + 8) * 64 + e) =
                make_float2(acc[mt][j][2], acc[mt][j][3]);
        }

    // S partial reduce (fixed order)
#pragma unroll
    for (int q = 0; q < 8; ++q) ps[myrow][myc * 8 + q] = sacc[q];
    __syncthreads();
    if (t < 64) {
        float s = 0.0f;
#pragma unroll
        for (int i = 0; i < 32; ++i) s += ps[i][t];
        g_spart[(bh * 4 + chunk) * 64 + t] = s;
    }

    // ---- fused reduce: last block for this bh normalizes the context -------
    __threadfence();
    __syncthreads();
    if (t == 0)
        s_last = (atomicAdd(&g_cnt[bh], 1) == 3);
    __syncthreads();
    if (!s_last) return;

    __threadfence();
    __shared__ float sinvS[64];
    if (t < 64) {
        const float* sp = g_spart + (size_t)bh * 256 + t;
        float s = sp[0] + sp[64] + sp[128] + sp[192];
        sinvS[t] = 1.0f / s;
    }
    __syncthreads();
    const float* cp = g_cpart + (size_t)bh * 16384;
    for (int idx = t; idx < 4096; idx += 256) {
        float c = cp[idx] + cp[idx + 4096] + cp[idx + 8192] + cp[idx + 12288];
        g_ctx16[(size_t)bh * 4096 + idx] = __float2half_rn(c * sinvS[idx >> 6]);
    }
    if (t == 0) g_cnt[bh] = 0;       // reset for next graph replay
}

// ---------------- Kernel 4: q-softmax + out via mma (256 tok/block, occ 6) ---
__global__ __launch_bounds__(256, 6) void out_mma(float* __restrict__ out)
{
    const int nbS = blockIdx.x;   // 0..15 (256-token superblock)
    const int bh  = blockIdx.y;
    const int b = bh >> 4, h = bh & 15;

    __shared__ __align__(16) __half sq[2][64 * 64];   // double-buffered
    __shared__ __align__(16) __half sctx[64 * 64];

    const unsigned sqS = (unsigned)__cvta_generic_to_shared(sq);
    const unsigned scS = (unsigned)__cvta_generic_to_shared(sctx);

    const int t    = threadIdx.x;
    const int lane = t & 31;
    const int warp = t >> 5;
    const int wt   = warp >> 1;
    const int we   = warp & 1;

    // ctx tile loaded once (cp.async, swizzled)
    {
        const int row = t >> 3, c = t & 7;
        unsigned s0 = (unsigned)(row * 128 + ((c ^ (row & 7)) << 4));
        unsigned s1 = (unsigned)((row + 32) * 128 + ((c ^ ((row + 32) & 7)) << 4));
        CP_ASYNC16(scS + s0, g_ctx16 + (size_t)bh * 4096 + row * 64 + c * 8);
        CP_ASYNC16(scS + s1, g_ctx16 + (size_t)bh * 4096 + (row + 32) * 64 + c * 8);
        CP_COMMIT();
    }

    const int myrow = t >> 3;
    const int myc   = t & 7;
    const __half* qbase = g_qkv16 +
        ((size_t)(b * GN_SEQ + nbS * 256)) * GNO + h * 64;

    // prefetch q raw for sub-tile 0
    uint4 qr0 = *(const uint4*)(qbase + (size_t)myrow * GNO + myc * 8);
    uint4 qr1 = *(const uint4*)(qbase + (size_t)(myrow + 32) * GNO + myc * 8);

    const int lr = lane & 15;
    const int ls = lane >> 4;
    const int rowB_l = (lane & 7) + (((lane >> 3) & 1) << 3);
    const int chB_l  = lane >> 4;
    const int g   = lane >> 2;
    const int tc2 = (lane & 3) * 2;

    const unsigned soff0 = (unsigned)(myrow * 128 + ((myc ^ (myrow & 7)) << 4));
    const unsigned soff1 = (unsigned)((myrow + 32) * 128 +
                                      ((myc ^ ((myrow + 32) & 7)) << 4));

    for (int s = 0; s < 4; ++s) {
        // exp in fp32; row sums via warp-local butterfly over the 8 lanes
        // that share a row (lanes 8g..8g+7 of a warp)
        float eq0[8], eq1[8];
        float psum0 = 0.0f, psum1 = 0.0f;
        {
            const __half2* hp = (const __half2*)&qr0;
#pragma unroll
            for (int q = 0; q < 4; ++q) {
                float2 f = __half22float2(hp[q]);
                eq0[q * 2]     = __expf(f.x);
                eq0[q * 2 + 1] = __expf(f.y);
                psum0 += eq0[q * 2] + eq0[q * 2 + 1];
            }
        }
        {
            const __half2* hp = (const __half2*)&qr1;
#pragma unroll
            for (int q = 0; q < 4; ++q) {
                float2 f = __half22float2(hp[q]);
                eq1[q * 2]     = __expf(f.x);
                eq1[q * 2 + 1] = __expf(f.y);
                psum1 += eq1[q * 2] + eq1[q * 2 + 1];
            }
        }
#pragma unroll
        for (int m = 1; m < 8; m <<= 1) {
            psum0 += __shfl_xor_sync(0xffffffffu, psum0, m);
            psum1 += __shfl_xor_sync(0xffffffffu, psum1, m);
        }
        const float inv0 = 0.125f / psum0;
        const float inv1 = 0.125f / psum1;

        // prefetch next sub-tile's q raw (latency hidden under mma below)
        if (s < 3) {
            const __half* qb = qbase + (size_t)((s + 1) * 64) * GNO;
            qr0 = *(const uint4*)(qb + (size_t)myrow * GNO + myc * 8);
            qr1 = *(const uint4*)(qb + (size_t)(myrow + 32) * GNO + myc * 8);
        }

        // scale + store fp16 swizzled into buffer (s & 1)
        const unsigned sbuf = sqS + (unsigned)(s & 1) * 8192;
        {
            uint4 outv;
            __half2* op = (__half2*)&outv;
#pragma unroll
            for (int q = 0; q < 4; ++q)
                op[q] = __floats2half2_rn(eq0[q * 2] * inv0, eq0[q * 2 + 1] * inv0);
            *(uint4*)((char*)sq + (s & 1) * 8192 + soff0) = outv;
        }
        {
            uint4 outv;
            __half2* op = (__half2*)&outv;
#pragma unroll
            for (int q = 0; q < 4; ++q)
                op[q] = __floats2half2_rn(eq1[q * 2] * inv1, eq1[q * 2 + 1] * inv1);
            *(uint4*)((char*)sq + (s & 1) * 8192 + soff1) = outv;
        }
        if (s == 0) CP_WAIT0();    // ctx resident before first mma
        __syncthreads();           // sq(s) visible to all warps

        // mma: warp tile 16 tok x 32 e, k = d (64)
        float acc[4][4];
#pragma unroll
        for (int i = 0; i < 4; ++i)
#pragma unroll
            for (int c = 0; c < 4; ++c) acc[i][c] = 0.0f;

#pragma unroll
        for (int ks = 0; ks < 4; ++ks) {
            unsigned aq[4], bc[2][4];
            {
                unsigned offA = (unsigned)(lr * 128 + (((2 * ks) + ls) ^ (lr & 7)) * 16);
                LDSM4(aq, sbuf + (unsigned)(wt * 16 * 128) + offA);
            }
            const int rB = ks * 16 + rowB_l;
#pragma unroll
            for (int p = 0; p < 2; ++p) {
                int ch = (we * 4 + p * 2 + chB_l) ^ (rB & 7);
                LDSM4T(bc[p], scS + (unsigned)(rB * 128 + ch * 16));
            }
#pragma unroll
            for (int p = 0; p < 2; ++p)
#pragma unroll
                for (int j = 0; j < 2; ++j)
                    MMA_F16(acc[p * 2 + j], aq, bc[p][2 * j], bc[p][2 * j + 1]);
        }

        // store this sub-tile
#pragma unroll
        for (int eb = 0; eb < 4; ++eb) {
            int tok = nbS * 256 + s * 64 + wt * 16 + g;
            int e   = we * 32 + eb * 8 + tc2;
            *(float2*)(out + ((size_t)bh * GN_SEQ + tok) * 64 + e) =
                make_float2(acc[eb][0], acc[eb][1]);
            *(float2*)(out + ((size_t)bh * GN_SEQ + tok + 8) * 64 + e) =
                make_float2(acc[eb][2], acc[eb][3]);
        }
        // no trailing sync: next sub-tile writes the OTHER sq buffer, and all
        // reads of this buffer precede the next __syncthreads in program order.
    }
}

// ---------------- launcher ----------------------------------------------------
extern "C" void kernel_launch(void* const* d_in, const int* in_sizes, int n_in,
                              void* d_out, int out_size)
{
    const float* x = (const float*)d_in[0];     // [4,4096,1024]
    const float* w = (const float*)d_in[1];     // [3072,1024]
    float* out = (float*)d_out;                 // [4,16,4096,64]

    cudaFuncSetAttribute(qkv_gemm_f16,
                         cudaFuncAttributeMaxDynamicSharedMemorySize, GEMM_SMEM);

    split_kernel<<<4096, 256>>>(x, w);

    dim3 gGemm(GNO / BN, GM / BM);              // (24, 128)
    qkv_gemm_f16<<<gGemm, 256, GEMM_SMEM>>>();

    dim3 gCtx(64, 4);
    ctx_partial_mma<<<gCtx, 256>>>();           // pipelined + fused reduce

    dim3 gOut(16, 64);                          // 256 tokens per block, occ 6
    out_mma<<<gOut, 256>>>(out);
}

// round 15
// speedup vs baseline: 1.0344x; 1.0344x over previous
#include <cuda_runtime.h>
#include <cuda_fp16.h>
#include <cstdint>

// Problem dims
#define GB     4
#define GN_SEQ 4096
#define GH     16
#define GD     64
#define GC     1024
#define GM     16384          // GB*GN_SEQ
#define GK     1024
#define GNO    3072           // 3*GC

// GEMM tiling: CTA 128x128, 8 warps of 64x32, BKK=64, 3 stages, occ 2
#define BM 128
#define BN 128
#define BKK 64
#define STAGES 3
#define STAGE_BYTES 32768               // A 16K | B 16K
#define GEMM_SMEM (STAGES * STAGE_BYTES)  // 96 KB -> 2 CTAs/SM

#define NCHUNK 8                        // ctx sequence-split (512 tokens each)

// ---------------- scratch (static device globals; no allocation) -------------
__device__ __half g_Ah[(size_t)GM * GK];       // 32 MB x fp16
__device__ __half g_Wh[(size_t)GNO * GK];      //  6 MB w fp16
__device__ __half g_qkv16[(size_t)GM * GNO];   // 96 MB qkv logits fp16
__device__ float  g_cpart[64 * NCHUNK * 64 * 64];
__device__ float  g_spart[64 * NCHUNK * 64];
__device__ __half g_ctx16[64 * 64 * 64];       // normalized context fp16 [bh][d][e]
__device__ int    g_cnt[64];                   // per-bh completion counters (0-init)

// ---------------- asm helpers ------------------------------------------------
#define LDSM4(r, addr)                                                         \
    asm volatile("ldmatrix.sync.aligned.m8n8.x4.shared.b16 {%0,%1,%2,%3},[%4];"\
                 : "=r"((r)[0]), "=r"((r)[1]), "=r"((r)[2]), "=r"((r)[3])      \
                 : "r"(addr))

#define LDSM4T(r, addr)                                                        \
    asm volatile("ldmatrix.sync.aligned.m8n8.x4.trans.shared.b16 "             \
                 "{%0,%1,%2,%3},[%4];"                                         \
                 : "=r"((r)[0]), "=r"((r)[1]), "=r"((r)[2]), "=r"((r)[3])      \
                 : "r"(addr))

#define MMA_F16(d, a, b0, b1)                                                  \
    asm volatile("mma.sync.aligned.m16n8k16.row.col.f32.f16.f16.f32 "          \
                 "{%0,%1,%2,%3},{%4,%5,%6,%7},{%8,%9},{%0,%1,%2,%3};"          \
                 : "+f"((d)[0]), "+f"((d)[1]), "+f"((d)[2]), "+f"((d)[3])      \
                 : "r"((a)[0]), "r"((a)[1]), "r"((a)[2]), "r"((a)[3]),         \
                   "r"(b0), "r"(b1))

#define CP_ASYNC16(dst, src)                                                   \
    asm volatile("cp.async.cg.shared.global [%0],[%1],16;" ::                  \
                 "r"(dst), "l"(src) : "memory")
#define CP_COMMIT() asm volatile("cp.async.commit_group;" ::: "memory")
#define CP_WAIT1()  asm volatile("cp.async.wait_group 1;" ::: "memory")
#define CP_WAIT0()  asm volatile("cp.async.wait_group 0;" ::: "memory")

// ---------------- Kernel 0: fp32 -> fp16 convert pre-pass --------------------
__global__ __launch_bounds__(256) void split_kernel(const float* __restrict__ x,
                                                    const float* __restrict__ w)
{
    const size_t A4 = (size_t)GM * GK / 4;
    const size_t W4 = (size_t)GNO * GK / 4;
    const size_t total = A4 + W4;
    size_t stride = (size_t)gridDim.x * blockDim.x;
    for (size_t i = (size_t)blockIdx.x * blockDim.x + threadIdx.x; i < total; i += stride) {
        if (i < A4) {
            float4 v = ((const float4*)x)[i];
            __half2 h0 = __floats2half2_rn(v.x, v.y);
            __half2 h1 = __floats2half2_rn(v.z, v.w);
            *(uint2*)(g_Ah + i * 4) =
                make_uint2(*(unsigned*)&h0, *(unsigned*)&h1);
        } else {
            size_t j = i - A4;
            float4 v = ((const float4*)w)[j];
            __half2 h0 = __floats2half2_rn(v.x, v.y);
            __half2 h1 = __floats2half2_rn(v.z, v.w);
            *(uint2*)(g_Wh + j * 4) =
                make_uint2(*(unsigned*)&h0, *(unsigned*)&h1);
        }
    }
}

// ---------------- GEMM stage loader -------------------------------------------
__device__ __forceinline__ void issue_stage(int kt, int bm, int bn,
                                            unsigned sbase, int t)
{
    const int k0 = kt * BKK;
    const unsigned buf = sbase + (kt % STAGES) * STAGE_BYTES;
#pragma unroll
    for (int j = 0; j < 4; ++j) {
        int idx = t + j * 256;          // 0..1023
        int row = idx >> 3;
        int c   = idx & 7;
        unsigned soff = (unsigned)(row * 128 + ((c ^ (row & 7)) << 4));
        const __half* ga = g_Ah + (size_t)(bm + row) * GK + k0 + c * 8;
        CP_ASYNC16(buf + soff, ga);
        const __half* gb = g_Wh + (size_t)(bn + row) * GK + k0 + c * 8;
        CP_ASYNC16(buf + 16384 + soff, gb);
    }
}

// ---------------- Kernel 1: QKV GEMM (single fp16 MMA, fp32 acc, occ 2) -----
__global__ __launch_bounds__(256, 2) void qkv_gemm_f16()
{
    extern __shared__ char smraw[];
    const unsigned sbase = (unsigned)__cvta_generic_to_shared(smraw);

    const int t    = threadIdx.x;
    const int bn   = blockIdx.x * BN;
    const int bm   = blockIdx.y * BM;
    const int lane = t & 31;
    const int warp = t >> 5;
    const int wm   = warp >> 2;
    const int wn   = warp & 3;

    const int lr = lane & 15;
    const int ls = lane >> 4;
    unsigned off[4];
#pragma unroll
    for (int g = 0; g < 4; ++g)
        off[g] = (unsigned)(lr * 128 + (((2 * g) + ls) ^ (lr & 7)) * 16);

    float acc[4][4][4];
#pragma unroll
    for (int i = 0; i < 4; ++i)
#pragma unroll
        for (int j = 0; j < 4; ++j)
#pragma unroll
            for (int c = 0; c < 4; ++c) acc[i][j][c] = 0.0f;

    issue_stage(0, bm, bn, sbase, t); CP_COMMIT();
    issue_stage(1, bm, bn, sbase, t); CP_COMMIT();

    const int NT = GK / BKK;   // 16
    for (int kt = 0; kt < NT; ++kt) {
        CP_WAIT1();
        __syncthreads();
        if (kt + 2 < NT)
            issue_stage(kt + 2, bm, bn, sbase, t);
        CP_COMMIT();

        const unsigned slot = sbase + (kt % STAGES) * STAGE_BYTES;
        const unsigned aBs  = slot +         (wm * 64) * 128;
        const unsigned bBs  = slot + 16384 + (wn * 32) * 128;

#pragma unroll
        for (int ks = 0; ks < 4; ++ks) {
            unsigned ah[4][4], bb[2][4];
#pragma unroll
            for (int mt = 0; mt < 4; ++mt)
                LDSM4(ah[mt], aBs + mt * 2048 + off[ks]);
#pragma unroll
            for (int p = 0; p < 2; ++p)
                LDSM4(bb[p], bBs + p * 2048 + off[ks]);
#pragma unroll
            for (int mt = 0; mt < 4; ++mt)
#pragma unroll
                for (int p = 0; p < 2; ++p)
#pragma unroll
                    for (int j = 0; j < 2; ++j)
                        MMA_F16(acc[mt][p * 2 + j], ah[mt], bb[p][j], bb[p][j + 2]);
        }
    }

    // epilogue -> fp16 logits
    const int g  = lane >> 2;
    const int tc = lane & 3;
#pragma unroll
    for (int mt = 0; mt < 4; ++mt)
#pragma unroll
        for (int nt = 0; nt < 4; ++nt) {
            int row = bm + wm * 64 + mt * 16 + g;
            int col = bn + wn * 32 + nt * 8 + tc * 2;
            *(__half2*)(g_qkv16 + (size_t)row * GNO + col) =
                __floats2half2_rn(acc[mt][nt][0], acc[mt][nt][1]);
            *(__half2*)(g_qkv16 + (size_t)(row + 8) * GNO + col) =
                __floats2half2_rn(acc[mt][nt][2], acc[mt][nt][3]);
        }
}

// ---------------- Kernel 2: ctx partial via mma (8 chunks) + fused reduce ----
__global__ __launch_bounds__(256) void ctx_partial_mma()
{
    const int bh    = blockIdx.x;
    const int chunk = blockIdx.y;       // 0..7 (512 tokens each)
    const int b = bh >> 4, h = bh & 15;

    __shared__ __align__(16) __half sek[64 * 64];      // [n][d] swizzled
    __shared__ __align__(16) __half sv[2][64 * 64];    // double-buffered v
    __shared__ float ps[32][64];
    __shared__ int   s_last;

    const unsigned ekS = (unsigned)__cvta_generic_to_shared(sek);
    const unsigned vS  = (unsigned)__cvta_generic_to_shared(sv);

    const int t    = threadIdx.x;
    const int lane = t & 31;
    const int warp = t >> 5;
    const int wd   = warp >> 2;
    const int we   = warp & 3;

    const int rowA_l = (lane & 7) + ((lane >> 4) << 3);
    const int chA_l  = (lane >> 3) & 1;
    const int rowB_l = (lane & 7) + (((lane >> 3) & 1) << 3);
    const int chB_l  = lane >> 4;

    float acc[2][2][4];
#pragma unroll
    for (int i = 0; i < 2; ++i)
#pragma unroll
        for (int j = 0; j < 2; ++j)
#pragma unroll
            for (int c = 0; c < 4; ++c) acc[i][j][c] = 0.0f;
    float sacc[8] = {0, 0, 0, 0, 0, 0, 0, 0};

    const __half* kbase = g_qkv16 + ((size_t)b * GN_SEQ) * GNO + 1024 + h * 64;
    const __half* vbase = kbase + 1024;

    const int myrow = t >> 3;
    const int myc   = t & 7;
    const unsigned soff0 = (unsigned)(myrow * 128 + ((myc ^ (myrow & 7)) << 4));
    const unsigned soff1 = (unsigned)((myrow + 32) * 128 +
                                      ((myc ^ ((myrow + 32) & 7)) << 4));

    const int NTILE = 512 / 64;   // 8 tiles per chunk

    // prologue: prefetch k raw for tile 0, issue v load for tile 0
    uint4 kr0, kr1;
    {
        const int n0 = chunk * 512;
        kr0 = *(const uint4*)(kbase + (size_t)(n0 + myrow) * GNO + myc * 8);
        kr1 = *(const uint4*)(kbase + (size_t)(n0 + myrow + 32) * GNO + myc * 8);
        CP_ASYNC16(vS + soff0, vbase + (size_t)(n0 + myrow) * GNO + myc * 8);
        CP_ASYNC16(vS + soff1, vbase + (size_t)(n0 + myrow + 32) * GNO + myc * 8);
        CP_COMMIT();
    }

    for (int tile = 0; tile < NTILE; ++tile) {
        const unsigned vbuf = vS + (unsigned)(tile & 1) * 8192;
        if (tile + 1 < NTILE) {
            const int n1 = chunk * 512 + (tile + 1) * 64;
            const unsigned vnext = vS + (unsigned)((tile + 1) & 1) * 8192;
            CP_ASYNC16(vnext + soff0, vbase + (size_t)(n1 + myrow) * GNO + myc * 8);
            CP_ASYNC16(vnext + soff1, vbase + (size_t)(n1 + myrow + 32) * GNO + myc * 8);
        }
        CP_COMMIT();

        {
            const uint4 raws[2] = {kr0, kr1};
#pragma unroll
            for (int j = 0; j < 2; ++j) {
                const __half2* hp = (const __half2*)&raws[j];
                float e[8];
#pragma unroll
                for (int q = 0; q < 4; ++q) {
                    float2 f = __half22float2(hp[q]);
                    e[q * 2]     = __expf(f.x);
                    e[q * 2 + 1] = __expf(f.y);
                }
#pragma unroll
                for (int q = 0; q < 8; ++q) sacc[q] += e[q];
                uint4 outv;
                __half2* op = (__half2*)&outv;
#pragma unroll
                for (int q = 0; q < 4; ++q)
                    op[q] = __floats2half2_rn(e[q * 2], e[q * 2 + 1]);
                *(uint4*)((char*)sek + (j ? soff1 : soff0)) = outv;
            }
        }
        if (tile + 1 < NTILE) {
            const int n1 = chunk * 512 + (tile + 1) * 64;
            kr0 = *(const uint4*)(kbase + (size_t)(n1 + myrow) * GNO + myc * 8);
            kr1 = *(const uint4*)(kbase + (size_t)(n1 + myrow + 32) * GNO + myc * 8);
        }
        CP_WAIT1();
        __syncthreads();

#pragma unroll
        for (int ks = 0; ks < 4; ++ks) {
            const int rA = ks * 16 + rowA_l;
            const int rB = ks * 16 + rowB_l;
            unsigned af[2][4], bf[4];
#pragma unroll
            for (int mt = 0; mt < 2; ++mt) {
                int ch = (wd * 4 + mt * 2 + chA_l) ^ (rA & 7);
                LDSM4T(af[mt], ekS + (unsigned)(rA * 128 + ch * 16));
            }
            {
                int ch = (we * 2 + chB_l) ^ (rB & 7);
                LDSM4T(bf, vbuf + (unsigned)(rB * 128 + ch * 16));
            }
#pragma unroll
            for (int mt = 0; mt < 2; ++mt)
#pragma unroll
                for (int j = 0; j < 2; ++j)
                    MMA_F16(acc[mt][j], af[mt], bf[2 * j], bf[2 * j + 1]);
        }
        __syncthreads();
    }

    // write C partials
    const int g   = lane >> 2;
    const int tc2 = (lane & 3) * 2;
    const size_t cbase = ((size_t)(bh * NCHUNK + chunk)) * 4096;
#pragma unroll
    for (int mt = 0; mt < 2; ++mt)
#pragma unroll
        for (int j = 0; j < 2; ++j) {
            int d = wd * 32 + mt * 16 + g;
            int e = we * 16 + j * 8 + tc2;
            *(float2*)(g_cpart + cbase + d * 64 + e) =
                make_float2(acc[mt][j][0], acc[mt][j][1]);
            *(float2*)(g_cpart + cbase + (d + 8) * 64 + e) =
                make_float2(acc[mt][j][2], acc[mt][j][3]);
        }

    // S partial reduce (fixed order)
#pragma unroll
    for (int q = 0; q < 8; ++q) ps[myrow][myc * 8 + q] = sacc[q];
    __syncthreads();
    if (t < 64) {
        float s = 0.0f;
#pragma unroll
        for (int i = 0; i < 32; ++i) s += ps[i][t];
        g_spart[(bh * NCHUNK + chunk) * 64 + t] = s;
    }

    // ---- fused reduce: last block for this bh normalizes the context -------
    __threadfence();
    __syncthreads();
    if (t == 0)
        s_last = (atomicAdd(&g_cnt[bh], 1) == NCHUNK - 1);
    __syncthreads();
    if (!s_last) return;

    __threadfence();
    __shared__ float sinvS[64];
    if (t < 64) {
        const float* sp = g_spart + (size_t)bh * (NCHUNK * 64) + t;
        float s = 0.0f;
#pragma unroll
        for (int j = 0; j < NCHUNK; ++j) s += sp[j * 64];
        sinvS[t] = 1.0f / s;
    }
    __syncthreads();
    const float* cp = g_cpart + (size_t)bh * (NCHUNK * 4096);
    for (int idx = t; idx < 4096; idx += 256) {
        float c = 0.0f;
#pragma unroll
        for (int j = 0; j < NCHUNK; ++j) c += cp[idx + j * 4096];
        g_ctx16[(size_t)bh * 4096 + idx] = __float2half_rn(c * sinvS[idx >> 6]);
    }
    if (t == 0) g_cnt[bh] = 0;       // reset for next graph replay
}

// ---------------- Kernel 4: q-softmax + out via mma (R12 config) -------------
__global__ __launch_bounds__(256) void out_mma(float* __restrict__ out)
{
    const int nbS = blockIdx.x;   // 0..15 (256-token superblock)
    const int bh  = blockIdx.y;
    const int b = bh >> 4, h = bh & 15;

    __shared__ __align__(16) __half sq[2][64 * 64];   // double-buffered
    __shared__ __align__(16) __half sctx[64 * 64];

    const unsigned sqS = (unsigned)__cvta_generic_to_shared(sq);
    const unsigned scS = (unsigned)__cvta_generic_to_shared(sctx);

    const int t    = threadIdx.x;
    const int lane = t & 31;
    const int warp = t >> 5;
    const int wt   = warp >> 1;
    const int we   = warp & 1;

    // ctx tile loaded once (cp.async, swizzled)
    {
        const int row = t >> 3, c = t & 7;
        unsigned s0 = (unsigned)(row * 128 + ((c ^ (row & 7)) << 4));
        unsigned s1 = (unsigned)((row + 32) * 128 + ((c ^ ((row + 32) & 7)) << 4));
        CP_ASYNC16(scS + s0, g_ctx16 + (size_t)bh * 4096 + row * 64 + c * 8);
        CP_ASYNC16(scS + s1, g_ctx16 + (size_t)bh * 4096 + (row + 32) * 64 + c * 8);
        CP_COMMIT();
    }

    const int myrow = t >> 3;
    const int myc   = t & 7;
    const __half* qbase = g_qkv16 +
        ((size_t)(b * GN_SEQ + nbS * 256)) * GNO + h * 64;

    // prefetch q raw for sub-tile 0
    uint4 qr0 = *(const uint4*)(qbase + (size_t)myrow * GNO + myc * 8);
    uint4 qr1 = *(const uint4*)(qbase + (size_t)(myrow + 32) * GNO + myc * 8);

    const int lr = lane & 15;
    const int ls = lane >> 4;
    const int rowB_l = (lane & 7) + (((lane >> 3) & 1) << 3);
    const int chB_l  = lane >> 4;
    const int g   = lane >> 2;
    const int tc2 = (lane & 3) * 2;

    const unsigned soff0 = (unsigned)(myrow * 128 + ((myc ^ (myrow & 7)) << 4));
    const unsigned soff1 = (unsigned)((myrow + 32) * 128 +
                                      ((myc ^ ((myrow + 32) & 7)) << 4));

    for (int s = 0; s < 4; ++s) {
        // exp in fp32; row sums via warp-local butterfly over the 8 lanes
        // that share a row (lanes 8g..8g+7 of a warp)
        float eq0[8], eq1[8];
        float psum0 = 0.0f, psum1 = 0.0f;
        {
            const __half2* hp = (const __half2*)&qr0;
#pragma unroll
            for (int q = 0; q < 4; ++q) {
                float2 f = __half22float2(hp[q]);
                eq0[q * 2]     = __expf(f.x);
                eq0[q * 2 + 1] = __expf(f.y);
                psum0 += eq0[q * 2] + eq0[q * 2 + 1];
            }
        }
        {
            const __half2* hp = (const __half2*)&qr1;
#pragma unroll
            for (int q = 0; q < 4; ++q) {
                float2 f = __half22float2(hp[q]);
                eq1[q * 2]     = __expf(f.x);
                eq1[q * 2 + 1] = __expf(f.y);
                psum1 += eq1[q * 2] + eq1[q * 2 + 1];
            }
        }
#pragma unroll
        for (int m = 1; m < 8; m <<= 1) {
            psum0 += __shfl_xor_sync(0xffffffffu, psum0, m);
            psum1 += __shfl_xor_sync(0xffffffffu, psum1, m);
        }
        const float inv0 = 0.125f / psum0;
        const float inv1 = 0.125f / psum1;

        // prefetch next sub-tile's q raw (latency hidden under mma below)
        if (s < 3) {
            const __half* qb = qbase + (size_t)((s + 1) * 64) * GNO;
            qr0 = *(const uint4*)(qb + (size_t)myrow * GNO + myc * 8);
            qr1 = *(const uint4*)(qb + (size_t)(myrow + 32) * GNO + myc * 8);
        }

        // scale + store fp16 swizzled into buffer (s & 1)
        const unsigned sbuf = sqS + (unsigned)(s & 1) * 8192;
        {
            uint4 outv;
            __half2* op = (__half2*)&outv;
#pragma unroll
            for (int q = 0; q < 4; ++q)
                op[q] = __floats2half2_rn(eq0[q * 2] * inv0, eq0[q * 2 + 1] * inv0);
            *(uint4*)((char*)sq + (s & 1) * 8192 + soff0) = outv;
        }
        {
            uint4 outv;
            __half2* op = (__half2*)&outv;
#pragma unroll
            for (int q = 0; q < 4; ++q)
                op[q] = __floats2half2_rn(eq1[q * 2] * inv1, eq1[q * 2 + 1] * inv1);
            *(uint4*)((char*)sq + (s & 1) * 8192 + soff1) = outv;
        }
        if (s == 0) CP_WAIT0();    // ctx resident before first mma
        __syncthreads();           // sq(s) visible to all warps

        // mma: warp tile 16 tok x 32 e, k = d (64)
        float acc[4][4];
#pragma unroll
        for (int i = 0; i < 4; ++i)
#pragma unroll
            for (int c = 0; c < 4; ++c) acc[i][c] = 0.0f;

#pragma unroll
        for (int ks = 0; ks < 4; ++ks) {
            unsigned aq[4], bc[2][4];
            {
                unsigned offA = (unsigned)(lr * 128 + (((2 * ks) + ls) ^ (lr & 7)) * 16);
                LDSM4(aq, sbuf + (unsigned)(wt * 16 * 128) + offA);
            }
            const int rB = ks * 16 + rowB_l;
#pragma unroll
            for (int p = 0; p < 2; ++p) {
                int ch = (we * 4 + p * 2 + chB_l) ^ (rB & 7);
                LDSM4T(bc[p], scS + (unsigned)(rB * 128 + ch * 16));
            }
#pragma unroll
            for (int p = 0; p < 2; ++p)
#pragma unroll
                for (int j = 0; j < 2; ++j)
                    MMA_F16(acc[p * 2 + j], aq, bc[p][2 * j], bc[p][2 * j + 1]);
        }

        // store this sub-tile
#pragma unroll
        for (int eb = 0; eb < 4; ++eb) {
            int tok = nbS * 256 + s * 64 + wt * 16 + g;
            int e   = we * 32 + eb * 8 + tc2;
            *(float2*)(out + ((size_t)bh * GN_SEQ + tok) * 64 + e) =
                make_float2(acc[eb][0], acc[eb][1]);
            *(float2*)(out + ((size_t)bh * GN_SEQ + tok + 8) * 64 + e) =
                make_float2(acc[eb][2], acc[eb][3]);
        }
        // no trailing sync: next sub-tile writes the OTHER sq buffer, and all
        // reads of this buffer precede the next __syncthreads in program order.
    }
}

// ---------------- launcher ----------------------------------------------------
extern "C" void kernel_launch(void* const* d_in, const int* in_sizes, int n_in,
                              void* d_out, int out_size)
{
    const float* x = (const float*)d_in[0];     // [4,4096,1024]
    const float* w = (const float*)d_in[1];     // [3072,1024]
    float* out = (float*)d_out;                 // [4,16,4096,64]

    cudaFuncSetAttribute(qkv_gemm_f16,
                         cudaFuncAttributeMaxDynamicSharedMemorySize, GEMM_SMEM);

    split_kernel<<<4096, 256>>>(x, w);

    dim3 gGemm(GNO / BN, GM / BM);              // (24, 128)
    qkv_gemm_f16<<<gGemm, 256, GEMM_SMEM>>>();

    dim3 gCtx(64, NCHUNK);
    ctx_partial_mma<<<gCtx, 256>>>();           // 512 blocks, fused reduce

    dim3 gOut(16, 64);                          // 256 tokens per block (R12)
    out_mma<<<gOut, 256>>>(out);
}

// round 16
// speedup vs baseline: 1.0369x; 1.0024x over previous
#include <cuda_runtime.h>
#include <cuda_fp16.h>
#include <cstdint>

// Problem dims
#define GB     4
#define GN_SEQ 4096
#define GH     16
#define GD     64
#define GC     1024
#define GM     16384          // GB*GN_SEQ
#define GK     1024
#define GNO    3072           // 3*GC

// GEMM tiling: CTA 128x128, 8 warps of 64x32, BKK=64, 3 stages, occ 2
#define BM 128
#define BN 128
#define BKK 64
#define STAGES 3
#define STAGE_BYTES 32768               // A 16K | B 16K
#define GEMM_SMEM (STAGES * STAGE_BYTES)  // 96 KB -> 2 CTAs/SM

#define NCHUNK 8                        // ctx sequence-split (512 tokens each)

// ---------------- scratch (static device globals; no allocation) -------------
__device__ __half g_Ah[(size_t)GM * GK];       // 32 MB x fp16
__device__ __half g_Wh[(size_t)GNO * GK];      //  6 MB w fp16
__device__ __half g_qkv16[(size_t)GM * GNO];   // 96 MB qkv logits fp16
__device__ float  g_cpart[64 * NCHUNK * 64 * 64];
__device__ float  g_spart[64 * NCHUNK * 64];
__device__ __half g_ctx16[64 * 64 * 64];       // normalized context fp16 [bh][d][e]
__device__ int    g_cnt[64];                   // per-bh completion counters (0-init)

// ---------------- asm helpers ------------------------------------------------
#define LDSM4(r, addr)                                                         \
    asm volatile("ldmatrix.sync.aligned.m8n8.x4.shared.b16 {%0,%1,%2,%3},[%4];"\
                 : "=r"((r)[0]), "=r"((r)[1]), "=r"((r)[2]), "=r"((r)[3])      \
                 : "r"(addr))

#define LDSM4T(r, addr)                                                        \
    asm volatile("ldmatrix.sync.aligned.m8n8.x4.trans.shared.b16 "             \
                 "{%0,%1,%2,%3},[%4];"                                         \
                 : "=r"((r)[0]), "=r"((r)[1]), "=r"((r)[2]), "=r"((r)[3])      \
                 : "r"(addr))

#define MMA_F16(d, a, b0, b1)                                                  \
    asm volatile("mma.sync.aligned.m16n8k16.row.col.f32.f16.f16.f32 "          \
                 "{%0,%1,%2,%3},{%4,%5,%6,%7},{%8,%9},{%0,%1,%2,%3};"          \
                 : "+f"((d)[0]), "+f"((d)[1]), "+f"((d)[2]), "+f"((d)[3])      \
                 : "r"((a)[0]), "r"((a)[1]), "r"((a)[2]), "r"((a)[3]),         \
                   "r"(b0), "r"(b1))

#define CP_ASYNC16(dst, src)                                                   \
    asm volatile("cp.async.cg.shared.global [%0],[%1],16;" ::                  \
                 "r"(dst), "l"(src) : "memory")
#define CP_COMMIT() asm volatile("cp.async.commit_group;" ::: "memory")
#define CP_WAIT1()  asm volatile("cp.async.wait_group 1;" ::: "memory")
#define CP_WAIT0()  asm volatile("cp.async.wait_group 0;" ::: "memory")

// ---------------- Kernel 0: fp32 -> fp16 convert pre-pass --------------------
// Streaming reads (__ldcs): x and w are consumed exactly once; keep L2 for the
// g_Ah/g_Wh writes the GEMM re-reads. Exact-cover grid: one float4 per thread.
__global__ __launch_bounds__(256) void split_kernel(const float* __restrict__ x,
                                                    const float* __restrict__ w)
{
    const size_t A4 = (size_t)GM * GK / 4;
    const size_t i  = (size_t)blockIdx.x * blockDim.x + threadIdx.x;
    if (i < A4) {
        float4 v = __ldcs((const float4*)x + i);
        __half2 h0 = __floats2half2_rn(v.x, v.y);
        __half2 h1 = __floats2half2_rn(v.z, v.w);
        *(uint2*)(g_Ah + i * 4) = make_uint2(*(unsigned*)&h0, *(unsigned*)&h1);
    } else {
        size_t j = i - A4;
        float4 v = __ldcs((const float4*)w + j);
        __half2 h0 = __floats2half2_rn(v.x, v.y);
        __half2 h1 = __floats2half2_rn(v.z, v.w);
        *(uint2*)(g_Wh + j * 4) = make_uint2(*(unsigned*)&h0, *(unsigned*)&h1);
    }
}

// ---------------- GEMM stage loader -------------------------------------------
__device__ __forceinline__ void issue_stage(int kt, int bm, int bn,
                                            unsigned sbase, int t)
{
    const int k0 = kt * BKK;
    const unsigned buf = sbase + (kt % STAGES) * STAGE_BYTES;
#pragma unroll
    for (int j = 0; j < 4; ++j) {
        int idx = t + j * 256;          // 0..1023
        int row = idx >> 3;
        int c   = idx & 7;
        unsigned soff = (unsigned)(row * 128 + ((c ^ (row & 7)) << 4));
        const __half* ga = g_Ah + (size_t)(bm + row) * GK + k0 + c * 8;
        CP_ASYNC16(buf + soff, ga);
        const __half* gb = g_Wh + (size_t)(bn + row) * GK + k0 + c * 8;
        CP_ASYNC16(buf + 16384 + soff, gb);
    }
}

// ---------------- Kernel 1: QKV GEMM (single fp16 MMA, fp32 acc, occ 2) -----
__global__ __launch_bounds__(256, 2) void qkv_gemm_f16()
{
    extern __shared__ char smraw[];
    const unsigned sbase = (unsigned)__cvta_generic_to_shared(smraw);

    const int t    = threadIdx.x;
    const int bn   = blockIdx.x * BN;
    const int bm   = blockIdx.y * BM;
    const int lane = t & 31;
    const int warp = t >> 5;
    const int wm   = warp >> 2;
    const int wn   = warp & 3;

    const int lr = lane & 15;
    const int ls = lane >> 4;
    unsigned off[4];
#pragma unroll
    for (int g = 0; g < 4; ++g)
        off[g] = (unsigned)(lr * 128 + (((2 * g) + ls) ^ (lr & 7)) * 16);

    float acc[4][4][4];
#pragma unroll
    for (int i = 0; i < 4; ++i)
#pragma unroll
        for (int j = 0; j < 4; ++j)
#pragma unroll
            for (int c = 0; c < 4; ++c) acc[i][j][c] = 0.0f;

    issue_stage(0, bm, bn, sbase, t); CP_COMMIT();
    issue_stage(1, bm, bn, sbase, t); CP_COMMIT();

    const int NT = GK / BKK;   // 16
    for (int kt = 0; kt < NT; ++kt) {
        CP_WAIT1();
        __syncthreads();
        if (kt + 2 < NT)
            issue_stage(kt + 2, bm, bn, sbase, t);
        CP_COMMIT();

        const unsigned slot = sbase + (kt % STAGES) * STAGE_BYTES;
        const unsigned aBs  = slot +         (wm * 64) * 128;
        const unsigned bBs  = slot + 16384 + (wn * 32) * 128;

#pragma unroll
        for (int ks = 0; ks < 4; ++ks) {
            unsigned ah[4][4], bb[2][4];
#pragma unroll
            for (int mt = 0; mt < 4; ++mt)
                LDSM4(ah[mt], aBs + mt * 2048 + off[ks]);
#pragma unroll
            for (int p = 0; p < 2; ++p)
                LDSM4(bb[p], bBs + p * 2048 + off[ks]);
#pragma unroll
            for (int mt = 0; mt < 4; ++mt)
#pragma unroll
                for (int p = 0; p < 2; ++p)
#pragma unroll
                    for (int j = 0; j < 2; ++j)
                        MMA_F16(acc[mt][p * 2 + j], ah[mt], bb[p][j], bb[p][j + 2]);
        }
    }

    // epilogue -> fp16 logits
    const int g  = lane >> 2;
    const int tc = lane & 3;
#pragma unroll
    for (int mt = 0; mt < 4; ++mt)
#pragma unroll
        for (int nt = 0; nt < 4; ++nt) {
            int row = bm + wm * 64 + mt * 16 + g;
            int col = bn + wn * 32 + nt * 8 + tc * 2;
            *(__half2*)(g_qkv16 + (size_t)row * GNO + col) =
                __floats2half2_rn(acc[mt][nt][0], acc[mt][nt][1]);
            *(__half2*)(g_qkv16 + (size_t)(row + 8) * GNO + col) =
                __floats2half2_rn(acc[mt][nt][2], acc[mt][nt][3]);
        }
}

// ---------------- Kernel 2: ctx partial via mma (8 chunks) + fused reduce ----
__global__ __launch_bounds__(256) void ctx_partial_mma()
{
    const int bh    = blockIdx.x;
    const int chunk = blockIdx.y;       // 0..7 (512 tokens each)
    const int b = bh >> 4, h = bh & 15;

    __shared__ __align__(16) __half sek[64 * 64];      // [n][d] swizzled
    __shared__ __align__(16) __half sv[2][64 * 64];    // double-buffered v
    __shared__ float ps[32][64];
    __shared__ int   s_last;

    const unsigned ekS = (unsigned)__cvta_generic_to_shared(sek);
    const unsigned vS  = (unsigned)__cvta_generic_to_shared(sv);

    const int t    = threadIdx.x;
    const int lane = t & 31;
    const int warp = t >> 5;
    const int wd   = warp >> 2;
    const int we   = warp & 3;

    const int rowA_l = (lane & 7) + ((lane >> 4) << 3);
    const int chA_l  = (lane >> 3) & 1;
    const int rowB_l = (lane & 7) + (((lane >> 3) & 1) << 3);
    const int chB_l  = lane >> 4;

    float acc[2][2][4];
#pragma unroll
    for (int i = 0; i < 2; ++i)
#pragma unroll
        for (int j = 0; j < 2; ++j)
#pragma unroll
            for (int c = 0; c < 4; ++c) acc[i][j][c] = 0.0f;
    float sacc[8] = {0, 0, 0, 0, 0, 0, 0, 0};

    const __half* kbase = g_qkv16 + ((size_t)b * GN_SEQ) * GNO + 1024 + h * 64;
    const __half* vbase = kbase + 1024;

    const int myrow = t >> 3;
    const int myc   = t & 7;
    const unsigned soff0 = (unsigned)(myrow * 128 + ((myc ^ (myrow & 7)) << 4));
    const unsigned soff1 = (unsigned)((myrow + 32) * 128 +
                                      ((myc ^ ((myrow + 32) & 7)) << 4));

    const int NTILE = 512 / 64;   // 8 tiles per chunk

    // prologue: prefetch k raw for tile 0, issue v load for tile 0
    uint4 kr0, kr1;
    {
        const int n0 = chunk * 512;
        kr0 = *(const uint4*)(kbase + (size_t)(n0 + myrow) * GNO + myc * 8);
        kr1 = *(const uint4*)(kbase + (size_t)(n0 + myrow + 32) * GNO + myc * 8);
        CP_ASYNC16(vS + soff0, vbase + (size_t)(n0 + myrow) * GNO + myc * 8);
        CP_ASYNC16(vS + soff1, vbase + (size_t)(n0 + myrow + 32) * GNO + myc * 8);
        CP_COMMIT();
    }

    for (int tile = 0; tile < NTILE; ++tile) {
        const unsigned vbuf = vS + (unsigned)(tile & 1) * 8192;
        if (tile + 1 < NTILE) {
            const int n1 = chunk * 512 + (tile + 1) * 64;
            const unsigned vnext = vS + (unsigned)((tile + 1) & 1) * 8192;
            CP_ASYNC16(vnext + soff0, vbase + (size_t)(n1 + myrow) * GNO + myc * 8);
            CP_ASYNC16(vnext + soff1, vbase + (size_t)(n1 + myrow + 32) * GNO + myc * 8);
        }
        CP_COMMIT();

        {
            const uint4 raws[2] = {kr0, kr1};
#pragma unroll
            for (int j = 0; j < 2; ++j) {
                const __half2* hp = (const __half2*)&raws[j];
                float e[8];
#pragma unroll
                for (int q = 0; q < 4; ++q) {
                    float2 f = __half22float2(hp[q]);
                    e[q * 2]     = __expf(f.x);
                    e[q * 2 + 1] = __expf(f.y);
                }
#pragma unroll
                for (int q = 0; q < 8; ++q) sacc[q] += e[q];
                uint4 outv;
                __half2* op = (__half2*)&outv;
#pragma unroll
                for (int q = 0; q < 4; ++q)
                    op[q] = __floats2half2_rn(e[q * 2], e[q * 2 + 1]);
                *(uint4*)((char*)sek + (j ? soff1 : soff0)) = outv;
            }
        }
        if (tile + 1 < NTILE) {
            const int n1 = chunk * 512 + (tile + 1) * 64;
            kr0 = *(const uint4*)(kbase + (size_t)(n1 + myrow) * GNO + myc * 8);
            kr1 = *(const uint4*)(kbase + (size_t)(n1 + myrow + 32) * GNO + myc * 8);
        }
        CP_WAIT1();
        __syncthreads();

#pragma unroll
        for (int ks = 0; ks < 4; ++ks) {
            const int rA = ks * 16 + rowA_l;
            const int rB = ks * 16 + rowB_l;
            unsigned af[2][4], bf[4];
#pragma unroll
            for (int mt = 0; mt < 2; ++mt) {
                int ch = (wd * 4 + mt * 2 + chA_l) ^ (rA & 7);
                LDSM4T(af[mt], ekS + (unsigned)(rA * 128 + ch * 16));
            }
            {
                int ch = (we * 2 + chB_l) ^ (rB & 7);
                LDSM4T(bf, vbuf + (unsigned)(rB * 128 + ch * 16));
            }
#pragma unroll
            for (int mt = 0; mt < 2; ++mt)
#pragma unroll
                for (int j = 0; j < 2; ++j)
                    MMA_F16(acc[mt][j], af[mt], bf[2 * j], bf[2 * j + 1]);
        }
        __syncthreads();
    }

    // write C partials
    const int g   = lane >> 2;
    const int tc2 = (lane & 3) * 2;
    const size_t cbase = ((size_t)(bh * NCHUNK + chunk)) * 4096;
#pragma unroll
    for (int mt = 0; mt < 2; ++mt)
#pragma unroll
        for (int j = 0; j < 2; ++j) {
            int d = wd * 32 + mt * 16 + g;
            int e = we * 16 + j * 8 + tc2;
            *(float2*)(g_cpart + cbase + d * 64 + e) =
                make_float2(acc[mt][j][0], acc[mt][j][1]);
            *(float2*)(g_cpart + cbase + (d + 8) * 64 + e) =
                make_float2(acc[mt][j][2], acc[mt][j][3]);
        }

    // S partial reduce (fixed order)
#pragma unroll
    for (int q = 0; q < 8; ++q) ps[myrow][myc * 8 + q] = sacc[q];
    __syncthreads();
    if (t < 64) {
        float s = 0.0f;
#pragma unroll
        for (int i = 0; i < 32; ++i) s += ps[i][t];
        g_spart[(bh * NCHUNK + chunk) * 64 + t] = s;
    }

    // ---- fused reduce: last block for this bh normalizes the context -------
    __threadfence();
    __syncthreads();
    if (t == 0)
        s_last = (atomicAdd(&g_cnt[bh], 1) == NCHUNK - 1);
    __syncthreads();
    if (!s_last) return;

    __threadfence();
    __shared__ float sinvS[64];
    if (t < 64) {
        const float* sp = g_spart + (size_t)bh * (NCHUNK * 64) + t;
        float s = 0.0f;
#pragma unroll
        for (int j = 0; j < NCHUNK; ++j) s += sp[j * 64];
        sinvS[t] = 1.0f / s;
    }
    __syncthreads();
    const float* cp = g_cpart + (size_t)bh * (NCHUNK * 4096);
    for (int idx = t; idx < 4096; idx += 256) {
        float c = 0.0f;
#pragma unroll
        for (int j = 0; j < NCHUNK; ++j) c += cp[idx + j * 4096];
        g_ctx16[(size_t)bh * 4096 + idx] = __float2half_rn(c * sinvS[idx >> 6]);
    }
    if (t == 0) g_cnt[bh] = 0;       // reset for next graph replay
}

// ---------------- Kernel 4: q-softmax + out via mma (R12 config) -------------
__global__ __launch_bounds__(256) void out_mma(float* __restrict__ out)
{
    const int nbS = blockIdx.x;   // 0..15 (256-token superblock)
    const int bh  = blockIdx.y;
    const int b = bh >> 4, h = bh & 15;

    __shared__ __align__(16) __half sq[2][64 * 64];   // double-buffered
    __shared__ __align__(16) __half sctx[64 * 64];

    const unsigned sqS = (unsigned)__cvta_generic_to_shared(sq);
    const unsigned scS = (unsigned)__cvta_generic_to_shared(sctx);

    const int t    = threadIdx.x;
    const int lane = t & 31;
    const int warp = t >> 5;
    const int wt   = warp >> 1;
    const int we   = warp & 1;

    // ctx tile loaded once (cp.async, swizzled)
    {
        const int row = t >> 3, c = t & 7;
        unsigned s0 = (unsigned)(row * 128 + ((c ^ (row & 7)) << 4));
        unsigned s1 = (unsigned)((row + 32) * 128 + ((c ^ ((row + 32) & 7)) << 4));
        CP_ASYNC16(scS + s0, g_ctx16 + (size_t)bh * 4096 + row * 64 + c * 8);
        CP_ASYNC16(scS + s1, g_ctx16 + (size_t)bh * 4096 + (row + 32) * 64 + c * 8);
        CP_COMMIT();
    }

    const int myrow = t >> 3;
    const int myc   = t & 7;
    const __half* qbase = g_qkv16 +
        ((size_t)(b * GN_SEQ + nbS * 256)) * GNO + h * 64;

    // prefetch q raw for sub-tile 0
    uint4 qr0 = *(const uint4*)(qbase + (size_t)myrow * GNO + myc * 8);
    uint4 qr1 = *(const uint4*)(qbase + (size_t)(myrow + 32) * GNO + myc * 8);

    const int lr = lane & 15;
    const int ls = lane >> 4;
    const int rowB_l = (lane & 7) + (((lane >> 3) & 1) << 3);
    const int chB_l  = lane >> 4;
    const int g   = lane >> 2;
    const int tc2 = (lane & 3) * 2;

    const unsigned soff0 = (unsigned)(myrow * 128 + ((myc ^ (myrow & 7)) << 4));
    const unsigned soff1 = (unsigned)((myrow + 32) * 128 +
                                      ((myc ^ ((myrow + 32) & 7)) << 4));

    for (int s = 0; s < 4; ++s) {
        // exp in fp32; row sums via warp-local butterfly over the 8 lanes
        // that share a row (lanes 8g..8g+7 of a warp)
        float eq0[8], eq1[8];
        float psum0 = 0.0f, psum1 = 0.0f;
        {
            const __half2* hp = (const __half2*)&qr0;
#pragma unroll
            for (int q = 0; q < 4; ++q) {
                float2 f = __half22float2(hp[q]);
                eq0[q * 2]     = __expf(f.x);
                eq0[q * 2 + 1] = __expf(f.y);
                psum0 += eq0[q * 2] + eq0[q * 2 + 1];
            }
        }
        {
            const __half2* hp = (const __half2*)&qr1;
#pragma unroll
            for (int q = 0; q < 4; ++q) {
                float2 f = __half22float2(hp[q]);
                eq1[q * 2]     = __expf(f.x);
                eq1[q * 2 + 1] = __expf(f.y);
                psum1 += eq1[q * 2] + eq1[q * 2 + 1];
            }
        }
#pragma unroll
        for (int m = 1; m < 8; m <<= 1) {
            psum0 += __shfl_xor_sync(0xffffffffu, psum0, m);
            psum1 += __shfl_xor_sync(0xffffffffu, psum1, m);
        }
        const float inv0 = 0.125f / psum0;
        const float inv1 = 0.125f / psum1;

        // prefetch next sub-tile's q raw (latency hidden under mma below)
        if (s < 3) {
            const __half* qb = qbase + (size_t)((s + 1) * 64) * GNO;
            qr0 = *(const uint4*)(qb + (size_t)myrow * GNO + myc * 8);
            qr1 = *(const uint4*)(qb + (size_t)(myrow + 32) * GNO + myc * 8);
        }

        // scale + store fp16 swizzled into buffer (s & 1)
        const unsigned sbuf = sqS + (unsigned)(s & 1) * 8192;
        {
            uint4 outv;
            __half2* op = (__half2*)&outv;
#pragma unroll
            for (int q = 0; q < 4; ++q)
                op[q] = __floats2half2_rn(eq0[q * 2] * inv0, eq0[q * 2 + 1] * inv0);
            *(uint4*)((char*)sq + (s & 1) * 8192 + soff0) = outv;
        }
        {
            uint4 outv;
            __half2* op = (__half2*)&outv;
#pragma unroll
            for (int q = 0; q < 4; ++q)
                op[q] = __floats2half2_rn(eq1[q * 2] * inv1, eq1[q * 2 + 1] * inv1);
            *(uint4*)((char*)sq + (s & 1) * 8192 + soff1) = outv;
        }
        if (s == 0) CP_WAIT0();    // ctx resident before first mma
        __syncthreads();           // sq(s) visible to all warps

        // mma: warp tile 16 tok x 32 e, k = d (64)
        float acc[4][4];
#pragma unroll
        for (int i = 0; i < 4; ++i)
#pragma unroll
            for (int c = 0; c < 4; ++c) acc[i][c] = 0.0f;

#pragma unroll
        for (int ks = 0; ks < 4; ++ks) {
            unsigned aq[4], bc[2][4];
            {
                unsigned offA = (unsigned)(lr * 128 + (((2 * ks) + ls) ^ (lr & 7)) * 16);
                LDSM4(aq, sbuf + (unsigned)(wt * 16 * 128) + offA);
            }
            const int rB = ks * 16 + rowB_l;
#pragma unroll
            for (int p = 0; p < 2; ++p) {
                int ch = (we * 4 + p * 2 + chB_l) ^ (rB & 7);
                LDSM4T(bc[p], scS + (unsigned)(rB * 128 + ch * 16));
            }
#pragma unroll
            for (int p = 0; p < 2; ++p)
#pragma unroll
                for (int j = 0; j < 2; ++j)
                    MMA_F16(acc[p * 2 + j], aq, bc[p][2 * j], bc[p][2 * j + 1]);
        }

        // store this sub-tile
#pragma unroll
        for (int eb = 0; eb < 4; ++eb) {
            int tok = nbS * 256 + s * 64 + wt * 16 + g;
            int e   = we * 32 + eb * 8 + tc2;
            *(float2*)(out + ((size_t)bh * GN_SEQ + tok) * 64 + e) =
                make_float2(acc[eb][0], acc[eb][1]);
            *(float2*)(out + ((size_t)bh * GN_SEQ + tok + 8) * 64 + e) =
                make_float2(acc[eb][2], acc[eb][3]);
        }
        // no trailing sync: next sub-tile writes the OTHER sq buffer, and all
        // reads of this buffer precede the next __syncthreads in program order.
    }
}

// ---------------- launcher ----------------------------------------------------
extern "C" void kernel_launch(void* const* d_in, const int* in_sizes, int n_in,
                              void* d_out, int out_size)
{
    const float* x = (const float*)d_in[0];     // [4,4096,1024]
    const float* w = (const float*)d_in[1];     // [3072,1024]
    float* out = (float*)d_out;                 // [4,16,4096,64]

    cudaFuncSetAttribute(qkv_gemm_f16,
                         cudaFuncAttributeMaxDynamicSharedMemorySize, GEMM_SMEM);

    // exact-cover grid: (GM*GK + GNO*GK)/4 float4 elements / 256 threads
    const int splitBlocks = (int)(((size_t)GM * GK / 4 + (size_t)GNO * GK / 4) / 256);
    split_kernel<<<splitBlocks, 256>>>(x, w);   // 7168 blocks

    dim3 gGemm(GNO / BN, GM / BM);              // (24, 128)
    qkv_gemm_f16<<<gGemm, 256, GEMM_SMEM>>>();

    dim3 gCtx(64, NCHUNK);
    ctx_partial_mma<<<gCtx, 256>>>();           // 512 blocks, fused reduce

    dim3 gOut(16, 64);                          // 256 tokens per block (R12)
    out_mma<<<gOut, 256>>>(out);
}

// round 17
// speedup vs baseline: 1.0402x; 1.0031x over previous
#include <cuda_runtime.h>
#include <cuda_fp16.h>
#include <cstdint>

// Problem dims
#define GB     4
#define GN_SEQ 4096
#define GH     16
#define GD     64
#define GC     1024
#define GM     16384          // GB*GN_SEQ
#define GK     1024
#define GNO    3072           // 3*GC

// GEMM tiling: CTA 128x128, 8 warps of 64x32, BKK=64, 3 stages, occ 2
#define BM 128
#define BN 128
#define BKK 64
#define STAGES 3
#define STAGE_BYTES 32768               // A 16K | B 16K
#define GEMM_SMEM (STAGES * STAGE_BYTES)  // 96 KB -> 2 CTAs/SM

#define NCHUNK 8                        // ctx sequence-split (512 tokens each)

// ---------------- scratch (static device globals; no allocation) -------------
__device__ __half g_Ah[(size_t)GM * GK];       // 32 MB x fp16
__device__ __half g_Wh[(size_t)GNO * GK];      //  6 MB w fp16
__device__ __half g_qkv16[(size_t)GM * GNO];   // 96 MB qkv logits fp16
__device__ float  g_cpart[64 * NCHUNK * 64 * 64];
__device__ float  g_spart[64 * NCHUNK * 64];
__device__ __half g_ctx16[64 * 64 * 64];       // normalized context fp16 [bh][d][e]
__device__ int    g_cnt[64];                   // per-bh completion counters (0-init)

// ---------------- asm helpers ------------------------------------------------
#define LDSM4(r, addr)                                                         \
    asm volatile("ldmatrix.sync.aligned.m8n8.x4.shared.b16 {%0,%1,%2,%3},[%4];"\
                 : "=r"((r)[0]), "=r"((r)[1]), "=r"((r)[2]), "=r"((r)[3])      \
                 : "r"(addr))

#define LDSM4T(r, addr)                                                        \
    asm volatile("ldmatrix.sync.aligned.m8n8.x4.trans.shared.b16 "             \
                 "{%0,%1,%2,%3},[%4];"                                         \
                 : "=r"((r)[0]), "=r"((r)[1]), "=r"((r)[2]), "=r"((r)[3])      \
                 : "r"(addr))

#define MMA_F16(d, a, b0, b1)                                                  \
    asm volatile("mma.sync.aligned.m16n8k16.row.col.f32.f16.f16.f32 "          \
                 "{%0,%1,%2,%3},{%4,%5,%6,%7},{%8,%9},{%0,%1,%2,%3};"          \
                 : "+f"((d)[0]), "+f"((d)[1]), "+f"((d)[2]), "+f"((d)[3])      \
                 : "r"((a)[0]), "r"((a)[1]), "r"((a)[2]), "r"((a)[3]),         \
                   "r"(b0), "r"(b1))

#define CP_ASYNC16(dst, src)                                                   \
    asm volatile("cp.async.cg.shared.global [%0],[%1],16;" ::                  \
                 "r"(dst), "l"(src) : "memory")
#define CP_COMMIT() asm volatile("cp.async.commit_group;" ::: "memory")
#define CP_WAIT1()  asm volatile("cp.async.wait_group 1;" ::: "memory")
#define CP_WAIT0()  asm volatile("cp.async.wait_group 0;" ::: "memory")

// ---------------- Kernel 0: fp32 -> fp16 convert pre-pass --------------------
// 2 float4 per thread, loads front-batched (MLP=2); streaming reads (__ldcs).
// A4 is even, so a thread's element pair never straddles the x/w boundary.
__global__ __launch_bounds__(256) void split_kernel(const float* __restrict__ x,
                                                    const float* __restrict__ w)
{
    const size_t A4 = (size_t)GM * GK / 4;
    const size_t i0 = ((size_t)blockIdx.x * blockDim.x + threadIdx.x) * 2;
    if (i0 < A4) {
        float4 v0 = __ldcs((const float4*)x + i0);
        float4 v1 = __ldcs((const float4*)x + i0 + 1);
        __half2 a0 = __floats2half2_rn(v0.x, v0.y);
        __half2 a1 = __floats2half2_rn(v0.z, v0.w);
        __half2 b0 = __floats2half2_rn(v1.x, v1.y);
        __half2 b1 = __floats2half2_rn(v1.z, v1.w);
        *(uint4*)(g_Ah + i0 * 4) =
            make_uint4(*(unsigned*)&a0, *(unsigned*)&a1,
                       *(unsigned*)&b0, *(unsigned*)&b1);
    } else {
        size_t j0 = i0 - A4;
        float4 v0 = __ldcs((const float4*)w + j0);
        float4 v1 = __ldcs((const float4*)w + j0 + 1);
        __half2 a0 = __floats2half2_rn(v0.x, v0.y);
        __half2 a1 = __floats2half2_rn(v0.z, v0.w);
        __half2 b0 = __floats2half2_rn(v1.x, v1.y);
        __half2 b1 = __floats2half2_rn(v1.z, v1.w);
        *(uint4*)(g_Wh + j0 * 4) =
            make_uint4(*(unsigned*)&a0, *(unsigned*)&a1,
                       *(unsigned*)&b0, *(unsigned*)&b1);
    }
}

// ---------------- GEMM stage loader -------------------------------------------
__device__ __forceinline__ void issue_stage(int kt, int bm, int bn,
                                            unsigned sbase, int t)
{
    const int k0 = kt * BKK;
    const unsigned buf = sbase + (kt % STAGES) * STAGE_BYTES;
#pragma unroll
    for (int j = 0; j < 4; ++j) {
        int idx = t + j * 256;          // 0..1023
        int row = idx >> 3;
        int c   = idx & 7;
        unsigned soff = (unsigned)(row * 128 + ((c ^ (row & 7)) << 4));
        const __half* ga = g_Ah + (size_t)(bm + row) * GK + k0 + c * 8;
        CP_ASYNC16(buf + soff, ga);
        const __half* gb = g_Wh + (size_t)(bn + row) * GK + k0 + c * 8;
        CP_ASYNC16(buf + 16384 + soff, gb);
    }
}

// ---------------- Kernel 1: QKV GEMM (single fp16 MMA, fp32 acc, occ 2) -----
__global__ __launch_bounds__(256, 2) void qkv_gemm_f16()
{
    extern __shared__ char smraw[];
    const unsigned sbase = (unsigned)__cvta_generic_to_shared(smraw);

    const int t    = threadIdx.x;
    const int bn   = blockIdx.x * BN;
    const int bm   = blockIdx.y * BM;
    const int lane = t & 31;
    const int warp = t >> 5;
    const int wm   = warp >> 2;
    const int wn   = warp & 3;

    const int lr = lane & 15;
    const int ls = lane >> 4;
    unsigned off[4];
#pragma unroll
    for (int g = 0; g < 4; ++g)
        off[g] = (unsigned)(lr * 128 + (((2 * g) + ls) ^ (lr & 7)) * 16);

    float acc[4][4][4];
#pragma unroll
    for (int i = 0; i < 4; ++i)
#pragma unroll
        for (int j = 0; j < 4; ++j)
#pragma unroll
            for (int c = 0; c < 4; ++c) acc[i][j][c] = 0.0f;

    issue_stage(0, bm, bn, sbase, t); CP_COMMIT();
    issue_stage(1, bm, bn, sbase, t); CP_COMMIT();

    const int NT = GK / BKK;   // 16
    for (int kt = 0; kt < NT; ++kt) {
        CP_WAIT1();
        __syncthreads();
        if (kt + 2 < NT)
            issue_stage(kt + 2, bm, bn, sbase, t);
        CP_COMMIT();

        const unsigned slot = sbase + (kt % STAGES) * STAGE_BYTES;
        const unsigned aBs  = slot +         (wm * 64) * 128;
        const unsigned bBs  = slot + 16384 + (wn * 32) * 128;

#pragma unroll
        for (int ks = 0; ks < 4; ++ks) {
            unsigned ah[4][4], bb[2][4];
#pragma unroll
            for (int mt = 0; mt < 4; ++mt)
                LDSM4(ah[mt], aBs + mt * 2048 + off[ks]);
#pragma unroll
            for (int p = 0; p < 2; ++p)
                LDSM4(bb[p], bBs + p * 2048 + off[ks]);
#pragma unroll
            for (int mt = 0; mt < 4; ++mt)
#pragma unroll
                for (int p = 0; p < 2; ++p)
#pragma unroll
                    for (int j = 0; j < 2; ++j)
                        MMA_F16(acc[mt][p * 2 + j], ah[mt], bb[p][j], bb[p][j + 2]);
        }
    }

    // epilogue -> fp16 logits
    const int g  = lane >> 2;
    const int tc = lane & 3;
#pragma unroll
    for (int mt = 0; mt < 4; ++mt)
#pragma unroll
        for (int nt = 0; nt < 4; ++nt) {
            int row = bm + wm * 64 + mt * 16 + g;
            int col = bn + wn * 32 + nt * 8 + tc * 2;
            *(__half2*)(g_qkv16 + (size_t)row * GNO + col) =
                __floats2half2_rn(acc[mt][nt][0], acc[mt][nt][1]);
            *(__half2*)(g_qkv16 + (size_t)(row + 8) * GNO + col) =
                __floats2half2_rn(acc[mt][nt][2], acc[mt][nt][3]);
        }
}

// ---------------- Kernel 2: ctx partial via mma (8 chunks) + fused reduce ----
__global__ __launch_bounds__(256) void ctx_partial_mma()
{
    const int bh    = blockIdx.x;
    const int chunk = blockIdx.y;       // 0..7 (512 tokens each)
    const int b = bh >> 4, h = bh & 15;

    __shared__ __align__(16) __half sek[64 * 64];      // [n][d] swizzled
    __shared__ __align__(16) __half sv[2][64 * 64];    // double-buffered v
    __shared__ float ps[32][64];
    __shared__ int   s_last;

    const unsigned ekS = (unsigned)__cvta_generic_to_shared(sek);
    const unsigned vS  = (unsigned)__cvta_generic_to_shared(sv);

    const int t    = threadIdx.x;
    const int lane = t & 31;
    const int warp = t >> 5;
    const int wd   = warp >> 2;
    const int we   = warp & 3;

    const int rowA_l = (lane & 7) + ((lane >> 4) << 3);
    const int chA_l  = (lane >> 3) & 1;
    const int rowB_l = (lane & 7) + (((lane >> 3) & 1) << 3);
    const int chB_l  = lane >> 4;

    float acc[2][2][4];
#pragma unroll
    for (int i = 0; i < 2; ++i)
#pragma unroll
        for (int j = 0; j < 2; ++j)
#pragma unroll
            for (int c = 0; c < 4; ++c) acc[i][j][c] = 0.0f;
    float sacc[8] = {0, 0, 0, 0, 0, 0, 0, 0};

    const __half* kbase = g_qkv16 + ((size_t)b * GN_SEQ) * GNO + 1024 + h * 64;
    const __half* vbase = kbase + 1024;

    const int myrow = t >> 3;
    const int myc   = t & 7;
    const unsigned soff0 = (unsigned)(myrow * 128 + ((myc ^ (myrow & 7)) << 4));
    const unsigned soff1 = (unsigned)((myrow + 32) * 128 +
                                      ((myc ^ ((myrow + 32) & 7)) << 4));

    const int NTILE = 512 / 64;   // 8 tiles per chunk

    // prologue: prefetch k raw for tile 0, issue v load for tile 0
    uint4 kr0, kr1;
    {
        const int n0 = chunk * 512;
        kr0 = *(const uint4*)(kbase + (size_t)(n0 + myrow) * GNO + myc * 8);
        kr1 = *(const uint4*)(kbase + (size_t)(n0 + myrow + 32) * GNO + myc * 8);
        CP_ASYNC16(vS + soff0, vbase + (size_t)(n0 + myrow) * GNO + myc * 8);
        CP_ASYNC16(vS + soff1, vbase + (size_t)(n0 + myrow + 32) * GNO + myc * 8);
        CP_COMMIT();
    }

    for (int tile = 0; tile < NTILE; ++tile) {
        const unsigned vbuf = vS + (unsigned)(tile & 1) * 8192;
        if (tile + 1 < NTILE) {
            const int n1 = chunk * 512 + (tile + 1) * 64;
            const unsigned vnext = vS + (unsigned)((tile + 1) & 1) * 8192;
            CP_ASYNC16(vnext + soff0, vbase + (size_t)(n1 + myrow) * GNO + myc * 8);
            CP_ASYNC16(vnext + soff1, vbase + (size_t)(n1 + myrow + 32) * GNO + myc * 8);
        }
        CP_COMMIT();

        {
            const uint4 raws[2] = {kr0, kr1};
#pragma unroll
            for (int j = 0; j < 2; ++j) {
                const __half2* hp = (const __half2*)&raws[j];
                float e[8];
#pragma unroll
                for (int q = 0; q < 4; ++q) {
                    float2 f = __half22float2(hp[q]);
                    e[q * 2]     = __expf(f.x);
                    e[q * 2 + 1] = __expf(f.y);
                }
#pragma unroll
                for (int q = 0; q < 8; ++q) sacc[q] += e[q];
                uint4 outv;
                __half2* op = (__half2*)&outv;
#pragma unroll
                for (int q = 0; q < 4; ++q)
                    op[q] = __floats2half2_rn(e[q * 2], e[q * 2 + 1]);
                *(uint4*)((char*)sek + (j ? soff1 : soff0)) = outv;
            }
        }
        if (tile + 1 < NTILE) {
            const int n1 = chunk * 512 + (tile + 1) * 64;
            kr0 = *(const uint4*)(kbase + (size_t)(n1 + myrow) * GNO + myc * 8);
            kr1 = *(const uint4*)(kbase + (size_t)(n1 + myrow + 32) * GNO + myc * 8);
        }
        CP_WAIT1();
        __syncthreads();

#pragma unroll
        for (int ks = 0; ks < 4; ++ks) {
            const int rA = ks * 16 + rowA_l;
            const int rB = ks * 16 + rowB_l;
            unsigned af[2][4], bf[4];
#pragma unroll
            for (int mt = 0; mt < 2; ++mt) {
                int ch = (wd * 4 + mt * 2 + chA_l) ^ (rA & 7);
                LDSM4T(af[mt], ekS + (unsigned)(rA * 128 + ch * 16));
            }
            {
                int ch = (we * 2 + chB_l) ^ (rB & 7);
                LDSM4T(bf, vbuf + (unsigned)(rB * 128 + ch * 16));
            }
#pragma unroll
            for (int mt = 0; mt < 2; ++mt)
#pragma unroll
                for (int j = 0; j < 2; ++j)
                    MMA_F16(acc[mt][j], af[mt], bf[2 * j], bf[2 * j + 1]);
        }
        __syncthreads();
    }

    // write C partials
    const int g   = lane >> 2;
    const int tc2 = (lane & 3) * 2;
    const size_t cbase = ((size_t)(bh * NCHUNK + chunk)) * 4096;
#pragma unroll
    for (int mt = 0; mt < 2; ++mt)
#pragma unroll
        for (int j = 0; j < 2; ++j) {
            int d = wd * 32 + mt * 16 + g;
            int e = we * 16 + j * 8 + tc2;
            *(float2*)(g_cpart + cbase + d * 64 + e) =
                make_float2(acc[mt][j][0], acc[mt][j][1]);
            *(float2*)(g_cpart + cbase + (d + 8) * 64 + e) =
                make_float2(acc[mt][j][2], acc[mt][j][3]);
        }

    // S partial reduce (fixed order)
#pragma unroll
    for (int q = 0; q < 8; ++q) ps[myrow][myc * 8 + q] = sacc[q];
    __syncthreads();
    if (t < 64) {
        float s = 0.0f;
#pragma unroll
        for (int i = 0; i < 32; ++i) s += ps[i][t];
        g_spart[(bh * NCHUNK + chunk) * 64 + t] = s;
    }

    // ---- fused reduce: last block for this bh normalizes the context -------
    __threadfence();
    __syncthreads();
    if (t == 0)
        s_last = (atomicAdd(&g_cnt[bh], 1) == NCHUNK - 1);
    __syncthreads();
    if (!s_last) return;

    __threadfence();
    __shared__ float sinvS[64];
    if (t < 64) {
        const float* sp = g_spart + (size_t)bh * (NCHUNK * 64) + t;
        float s = 0.0f;
#pragma unroll
        for (int j = 0; j < NCHUNK; ++j) s += sp[j * 64];
        sinvS[t] = 1.0f / s;
    }
    __syncthreads();
    const float* cp = g_cpart + (size_t)bh * (NCHUNK * 4096);
    for (int idx = t; idx < 4096; idx += 256) {
        float c = 0.0f;
#pragma unroll
        for (int j = 0; j < NCHUNK; ++j) c += cp[idx + j * 4096];
        g_ctx16[(size_t)bh * 4096 + idx] = __float2half_rn(c * sinvS[idx >> 6]);
    }
    if (t == 0) g_cnt[bh] = 0;       // reset for next graph replay
}

// ---------------- Kernel 4: q-softmax + out via mma (R12 config) -------------
__global__ __launch_bounds__(256) void out_mma(float* __restrict__ out)
{
    const int nbS = blockIdx.x;   // 0..15 (256-token superblock)
    const int bh  = blockIdx.y;
    const int b = bh >> 4, h = bh & 15;

    __shared__ __align__(16) __half sq[2][64 * 64];   // double-buffered
    __shared__ __align__(16) __half sctx[64 * 64];

    const unsigned sqS = (unsigned)__cvta_generic_to_shared(sq);
    const unsigned scS = (unsigned)__cvta_generic_to_shared(sctx);

    const int t    = threadIdx.x;
    const int lane = t & 31;
    const int warp = t >> 5;
    const int wt   = warp >> 1;
    const int we   = warp & 1;

    // ctx tile loaded once (cp.async, swizzled)
    {
        const int row = t >> 3, c = t & 7;
        unsigned s0 = (unsigned)(row * 128 + ((c ^ (row & 7)) << 4));
        unsigned s1 = (unsigned)((row + 32) * 128 + ((c ^ ((row + 32) & 7)) << 4));
        CP_ASYNC16(scS + s0, g_ctx16 + (size_t)bh * 4096 + row * 64 + c * 8);
        CP_ASYNC16(scS + s1, g_ctx16 + (size_t)bh * 4096 + (row + 32) * 64 + c * 8);
        CP_COMMIT();
    }

    const int myrow = t >> 3;
    const int myc   = t & 7;
    const __half* qbase = g_qkv16 +
        ((size_t)(b * GN_SEQ + nbS * 256)) * GNO + h * 64;

    // prefetch q raw for sub-tile 0
    uint4 qr0 = *(const uint4*)(qbase + (size_t)myrow * GNO + myc * 8);
    uint4 qr1 = *(const uint4*)(qbase + (size_t)(myrow + 32) * GNO + myc * 8);

    const int lr = lane & 15;
    const int ls = lane >> 4;
    const int rowB_l = (lane & 7) + (((lane >> 3) & 1) << 3);
    const int chB_l  = lane >> 4;
    const int g   = lane >> 2;
    const int tc2 = (lane & 3) * 2;

    const unsigned soff0 = (unsigned)(myrow * 128 + ((myc ^ (myrow & 7)) << 4));
    const unsigned soff1 = (unsigned)((myrow + 32) * 128 +
                                      ((myc ^ ((myrow + 32) & 7)) << 4));

    for (int s = 0; s < 4; ++s) {
        // exp in fp32; row sums via warp-local butterfly over the 8 lanes
        // that share a row (lanes 8g..8g+7 of a warp)
        float eq0[8], eq1[8];
        float psum0 = 0.0f, psum1 = 0.0f;
        {
            const __half2* hp = (const __half2*)&qr0;
#pragma unroll
            for (int q = 0; q < 4; ++q) {
                float2 f = __half22float2(hp[q]);
                eq0[q * 2]     = __expf(f.x);
                eq0[q * 2 + 1] = __expf(f.y);
                psum0 += eq0[q * 2] + eq0[q * 2 + 1];
            }
        }
        {
            const __half2* hp = (const __half2*)&qr1;
#pragma unroll
            for (int q = 0; q < 4; ++q) {
                float2 f = __half22float2(hp[q]);
                eq1[q * 2]     = __expf(f.x);
                eq1[q * 2 + 1] = __expf(f.y);
                psum1 += eq1[q * 2] + eq1[q * 2 + 1];
            }
        }
#pragma unroll
        for (int m = 1; m < 8; m <<= 1) {
            psum0 += __shfl_xor_sync(0xffffffffu, psum0, m);
            psum1 += __shfl_xor_sync(0xffffffffu, psum1, m);
        }
        const float inv0 = 0.125f / psum0;
        const float inv1 = 0.125f / psum1;

        // prefetch next sub-tile's q raw (latency hidden under mma below)
        if (s < 3) {
            const __half* qb = qbase + (size_t)((s + 1) * 64) * GNO;
            qr0 = *(const uint4*)(qb + (size_t)myrow * GNO + myc * 8);
            qr1 = *(const uint4*)(qb + (size_t)(myrow + 32) * GNO + myc * 8);
        }

        // scale + store fp16 swizzled into buffer (s & 1)
        const unsigned sbuf = sqS + (unsigned)(s & 1) * 8192;
        {
            uint4 outv;
            __half2* op = (__half2*)&outv;
#pragma unroll
            for (int q = 0; q < 4; ++q)
                op[q] = __floats2half2_rn(eq0[q * 2] * inv0, eq0[q * 2 + 1] * inv0);
            *(uint4*)((char*)sq + (s & 1) * 8192 + soff0) = outv;
        }
        {
            uint4 outv;
            __half2* op = (__half2*)&outv;
#pragma unroll
            for (int q = 0; q < 4; ++q)
                op[q] = __floats2half2_rn(eq1[q * 2] * inv1, eq1[q * 2 + 1] * inv1);
            *(uint4*)((char*)sq + (s & 1) * 8192 + soff1) = outv;
        }
        if (s == 0) CP_WAIT0();    // ctx resident before first mma
        __syncthreads();           // sq(s) visible to all warps

        // mma: warp tile 16 tok x 32 e, k = d (64)
        float acc[4][4];
#pragma unroll
        for (int i = 0; i < 4; ++i)
#pragma unroll
            for (int c = 0; c < 4; ++c) acc[i][c] = 0.0f;

#pragma unroll
        for (int ks = 0; ks < 4; ++ks) {
            unsigned aq[4], bc[2][4];
            {
                unsigned offA = (unsigned)(lr * 128 + (((2 * ks) + ls) ^ (lr & 7)) * 16);
                LDSM4(aq, sbuf + (unsigned)(wt * 16 * 128) + offA);
            }
            const int rB = ks * 16 + rowB_l;
#pragma unroll
            for (int p = 0; p < 2; ++p) {
                int ch = (we * 4 + p * 2 + chB_l) ^ (rB & 7);
                LDSM4T(bc[p], scS + (unsigned)(rB * 128 + ch * 16));
            }
#pragma unroll
            for (int p = 0; p < 2; ++p)
#pragma unroll
                for (int j = 0; j < 2; ++j)
                    MMA_F16(acc[p * 2 + j], aq, bc[p][2 * j], bc[p][2 * j + 1]);
        }

        // store this sub-tile
#pragma unroll
        for (int eb = 0; eb < 4; ++eb) {
            int tok = nbS * 256 + s * 64 + wt * 16 + g;
            int e   = we * 32 + eb * 8 + tc2;
            *(float2*)(out + ((size_t)bh * GN_SEQ + tok) * 64 + e) =
                make_float2(acc[eb][0], acc[eb][1]);
            *(float2*)(out + ((size_t)bh * GN_SEQ + tok + 8) * 64 + e) =
                make_float2(acc[eb][2], acc[eb][3]);
        }
        // no trailing sync: next sub-tile writes the OTHER sq buffer, and all
        // reads of this buffer precede the next __syncthreads in program order.
    }
}

// ---------------- launcher ----------------------------------------------------
extern "C" void kernel_launch(void* const* d_in, const int* in_sizes, int n_in,
                              void* d_out, int out_size)
{
    const float* x = (const float*)d_in[0];     // [4,4096,1024]
    const float* w = (const float*)d_in[1];     // [3072,1024]
    float* out = (float*)d_out;                 // [4,16,4096,64]

    cudaFuncSetAttribute(qkv_gemm_f16,
                         cudaFuncAttributeMaxDynamicSharedMemorySize, GEMM_SMEM);

    // exact-cover grid: total float4 / (2 per thread) / 256 threads
    const int splitBlocks = (int)(((size_t)GM * GK / 4 + (size_t)GNO * GK / 4) / 512);
    split_kernel<<<splitBlocks, 256>>>(x, w);   // 9728 blocks

    dim3 gGemm(GNO / BN, GM / BM);              // (24, 128)
    qkv_gemm_f16<<<gGemm, 256, GEMM_SMEM>>>();

    dim3 gCtx(64, NCHUNK);
    ctx_partial_mma<<<gCtx, 256>>>();           // 512 blocks, fused reduce

    dim3 gOut(16, 64);                          // 256 tokens per block (R12)
    out_mma<<<gOut, 256>>>(out);
}